// round 5
// baseline (speedup 1.0000x reference)
#include <cuda_runtime.h>
#include <math.h>

#define NN 100000
#define NE 3200000
#define NG 64
#define D 32
#define INF 128
#define NPAD 102400   // 1024 threads * 100 counters

// ---- scratch ----
__device__ float g_rhsA[NN * D];
__device__ float g_rhsB[NN * D];
__device__ float g_self[NN * D];
__device__ float g_h[NN * D];
__device__ float g_pool[NG * D];
__device__ int   g_counts[NPAD];
__device__ int   g_offs[NPAD + 1];
__device__ int   g_cursor[NPAD];
__device__ int   g_csrc[NE];

// ------------------------------------------------------------------
__global__ void zero_kernel() {
    int i = blockIdx.x * blockDim.x + threadIdx.x;
    if (i < NPAD) g_counts[i] = 0;
    if (i < NG * D) g_pool[i] = 0.f;
}

__global__ void hist_kernel(const int* __restrict__ dst) {
    int i = blockIdx.x * blockDim.x + threadIdx.x;
    int b = i * 4;
    if (b < NE) {
        int4 d = *(const int4*)&dst[b];
        atomicAdd(&g_counts[d.x], 1);
        atomicAdd(&g_counts[d.y], 1);
        atomicAdd(&g_counts[d.z], 1);
        atomicAdd(&g_counts[d.w], 1);
    }
}

// single-block scan: 1024 threads x 100 contiguous counters each
__global__ void __launch_bounds__(1024) scan_all() {
    const int CH = 100;
    int tid = threadIdx.x;
    int lane = tid & 31, wid = tid >> 5;
    int base = tid * CH;
    int s = 0;
#pragma unroll
    for (int i = 0; i < CH; i += 4) {
        int4 v = *(const int4*)&g_counts[base + i];
        s += v.x + v.y + v.z + v.w;
    }
    int pre = s;
#pragma unroll
    for (int dd = 1; dd < 32; dd <<= 1) {
        int t = __shfl_up_sync(0xffffffffu, pre, dd);
        if (lane >= dd) pre += t;
    }
    __shared__ int wsum[32];
    if (lane == 31) wsum[wid] = pre;
    __syncthreads();
    if (wid == 0) {
        int v = wsum[lane];
        int p = v;
#pragma unroll
        for (int dd = 1; dd < 32; dd <<= 1) {
            int t = __shfl_up_sync(0xffffffffu, p, dd);
            if (lane >= dd) p += t;
        }
        wsum[lane] = p - v;
    }
    __syncthreads();
    int run = wsum[wid] + (pre - s);
#pragma unroll
    for (int i = 0; i < CH; i += 4) {
        int4 c = *(const int4*)&g_counts[base + i];
        int4 o;
        o.x = run; run += c.x;
        o.y = run; run += c.y;
        o.z = run; run += c.z;
        o.w = run; run += c.w;
        *(int4*)&g_offs[base + i]   = o;
        *(int4*)&g_cursor[base + i] = o;
    }
}

__global__ void scatter_kernel(const int* __restrict__ src, const int* __restrict__ dst) {
    int i = blockIdx.x * blockDim.x + threadIdx.x;
    int b = i * 4;
    if (b < NE) {
        int4 s4 = *(const int4*)&src[b];
        int4 d4 = *(const int4*)&dst[b];
        int p;
        p = atomicAdd(&g_cursor[d4.x], 1); g_csrc[p] = s4.x;
        p = atomicAdd(&g_cursor[d4.y], 1); g_csrc[p] = s4.y;
        p = atomicAdd(&g_cursor[d4.z], 1); g_csrc[p] = s4.z;
        p = atomicAdd(&g_cursor[d4.w], 1); g_csrc[p] = s4.w;
    }
}

// ------------------------------------------------------------------
// Layer 0: rhsA = x@Wn0, self = x@Ws0  (register blocked, fp32).
__global__ void __launch_bounds__(64) gemm0_kernel(const float* __restrict__ x,
                                                   const float* __restrict__ Wn0,
                                                   const float* __restrict__ Ws0) {
    __shared__ float Wsh[INF][64];
    __shared__ float xs[64][33];
    int tid = threadIdx.x;
    for (int idx = tid; idx < INF * D; idx += 64) {
        int k = idx >> 5, c = idx & 31;
        Wsh[k][c]      = Wn0[idx];
        Wsh[k][c + 32] = Ws0[idx];
    }
    int n0 = blockIdx.x * 64;
    int ng = tid >> 2, cg = tid & 3;
    int c0 = cg * 16;
    float acc[4][16];
#pragma unroll
    for (int i = 0; i < 4; i++)
#pragma unroll
        for (int j = 0; j < 16; j++) acc[i][j] = 0.f;

    for (int kt = 0; kt < 4; kt++) {
        __syncthreads();
        for (int idx = tid; idx < 64 * 32; idx += 64) {
            int nl = idx >> 5, j = idx & 31;
            int n = n0 + nl;
            xs[nl][j] = (n < NN) ? x[n * INF + kt * 32 + j] : 0.f;
        }
        __syncthreads();
#pragma unroll 4
        for (int k = 0; k < 32; k++) {
            float xv[4];
#pragma unroll
            for (int i = 0; i < 4; i++) xv[i] = xs[ng * 4 + i][k];
            const float* wrow = &Wsh[kt * 32 + k][c0];
            float4 w0 = *(const float4*)&wrow[0];
            float4 w1 = *(const float4*)&wrow[4];
            float4 w2 = *(const float4*)&wrow[8];
            float4 w3 = *(const float4*)&wrow[12];
#pragma unroll
            for (int i = 0; i < 4; i++) {
                float xi = xv[i];
                acc[i][0]  = fmaf(xi, w0.x, acc[i][0]);
                acc[i][1]  = fmaf(xi, w0.y, acc[i][1]);
                acc[i][2]  = fmaf(xi, w0.z, acc[i][2]);
                acc[i][3]  = fmaf(xi, w0.w, acc[i][3]);
                acc[i][4]  = fmaf(xi, w1.x, acc[i][4]);
                acc[i][5]  = fmaf(xi, w1.y, acc[i][5]);
                acc[i][6]  = fmaf(xi, w1.z, acc[i][6]);
                acc[i][7]  = fmaf(xi, w1.w, acc[i][7]);
                acc[i][8]  = fmaf(xi, w2.x, acc[i][8]);
                acc[i][9]  = fmaf(xi, w2.y, acc[i][9]);
                acc[i][10] = fmaf(xi, w2.z, acc[i][10]);
                acc[i][11] = fmaf(xi, w2.w, acc[i][11]);
                acc[i][12] = fmaf(xi, w3.x, acc[i][12]);
                acc[i][13] = fmaf(xi, w3.y, acc[i][13]);
                acc[i][14] = fmaf(xi, w3.z, acc[i][14]);
                acc[i][15] = fmaf(xi, w3.w, acc[i][15]);
            }
        }
    }
#pragma unroll
    for (int i = 0; i < 4; i++) {
        int n = n0 + ng * 4 + i;
        if (n >= NN) break;
        float* dstp = (cg < 2) ? &g_rhsA[n * D + c0] : &g_self[n * D + (c0 - 32)];
#pragma unroll
        for (int j = 0; j < 4; j++) {
            float4 f = make_float4(acc[i][4 * j], acc[i][4 * j + 1],
                                   acc[i][4 * j + 2], acc[i][4 * j + 3]);
            *(float4*)&dstp[4 * j] = f;
        }
    }
}

// ------------------------------------------------------------------
// Warp-coalesced gather core: lane l loads csrc[e+l] (one coalesced load = 32
// indices), broadcast via shfl, 8-deep independent row-gather batches.
__device__ __forceinline__ float gather_rows(const float* __restrict__ rin,
                                             int beg, int end, int lane) {
    float acc = 0.f;
    int e = beg;
    while (e < end) {
        int rem = end - e;
        int cnt = rem < 32 ? rem : 32;
        int idx = (lane < cnt) ? g_csrc[e + lane] : 0;
        int k = 0;
        for (; k + 8 <= cnt; k += 8) {
            int s0 = __shfl_sync(0xffffffffu, idx, k);
            int s1 = __shfl_sync(0xffffffffu, idx, k + 1);
            int s2 = __shfl_sync(0xffffffffu, idx, k + 2);
            int s3 = __shfl_sync(0xffffffffu, idx, k + 3);
            int s4 = __shfl_sync(0xffffffffu, idx, k + 4);
            int s5 = __shfl_sync(0xffffffffu, idx, k + 5);
            int s6 = __shfl_sync(0xffffffffu, idx, k + 6);
            int s7 = __shfl_sync(0xffffffffu, idx, k + 7);
            float v0 = rin[s0 * D + lane];
            float v1 = rin[s1 * D + lane];
            float v2 = rin[s2 * D + lane];
            float v3 = rin[s3 * D + lane];
            float v4 = rin[s4 * D + lane];
            float v5 = rin[s5 * D + lane];
            float v6 = rin[s6 * D + lane];
            float v7 = rin[s7 * D + lane];
            acc += ((v0 + v1) + (v2 + v3)) + ((v4 + v5) + (v6 + v7));
        }
        for (; k < cnt; k++) {
            int s = __shfl_sync(0xffffffffu, idx, k);
            acc += rin[s * D + lane];
        }
        e += cnt;
    }
    return acc;
}

// Fused agg + next-layer transform. Warp per node, lane = dim.
__global__ void __launch_bounds__(256) agg_fused(const float* __restrict__ bn,
                                                 const float* __restrict__ WnN,
                                                 const float* __restrict__ WsN,
                                                 int rd) {
    __shared__ float sWn[D * D], sWs[D * D];
    int tid = threadIdx.x;
    for (int i = tid; i < D * D; i += 256) { sWn[i] = WnN[i]; sWs[i] = WsN[i]; }
    __syncthreads();

    int gw = (blockIdx.x * blockDim.x + tid) >> 5;
    if (gw >= NN) return;
    int lane = tid & 31;
    const float* __restrict__ rin = rd ? g_rhsB : g_rhsA;
    float* __restrict__ rout = rd ? g_rhsA : g_rhsB;

    float acc = g_self[gw * D + lane] + bn[lane]
              + gather_rows(rin, g_offs[gw], g_offs[gw + 1], lane);
    float h = fmaxf(acc, 0.f);

    float ar = 0.f, as_ = 0.f;
#pragma unroll
    for (int k = 0; k < D; k++) {
        float hk = __shfl_sync(0xffffffffu, h, k);
        ar  = fmaf(hk, sWn[k * D + lane], ar);
        as_ = fmaf(hk, sWs[k * D + lane], as_);
    }
    rout[gw * D + lane]   = ar;
    g_self[gw * D + lane] = as_;
}

// Last layer: gather only, writes g_h.
__global__ void __launch_bounds__(256) agg_last(const float* __restrict__ bn, int rd) {
    int tid = threadIdx.x;
    int gw = (blockIdx.x * blockDim.x + tid) >> 5;
    if (gw >= NN) return;
    int lane = tid & 31;
    const float* __restrict__ rin = rd ? g_rhsB : g_rhsA;

    float acc = g_self[gw * D + lane] + bn[lane]
              + gather_rows(rin, g_offs[gw], g_offs[gw + 1], lane);
    g_h[gw * D + lane] = fmaxf(acc, 0.f);
}

// ------------------------------------------------------------------
__global__ void __launch_bounds__(256) pool_kernel(const int* __restrict__ gid) {
    __shared__ float ps[NG * D];
    int tid = threadIdx.x;
    for (int i = tid; i < NG * D; i += 256) ps[i] = 0.f;
    __syncthreads();
    int d = tid & 31;
    int base = blockIdx.x * 1024;
    for (int i = tid >> 5; i < 1024; i += 8) {
        int n = base + i;
        if (n < NN) atomicAdd(&ps[gid[n] * D + d], g_h[n * D + d]);
    }
    __syncthreads();
    for (int i = tid; i < NG * D; i += 256) {
        float v = ps[i];
        if (v != 0.f) atomicAdd(&g_pool[i], v);
    }
}

__global__ void mlp_kernel(const float* __restrict__ Wfc1, const float* __restrict__ bfc1,
                           const float* __restrict__ Wout, const float* __restrict__ bout,
                           float* __restrict__ out) {
    int g = threadIdx.x;
    if (g >= NG) return;
    float hv[D];
#pragma unroll
    for (int k = 0; k < D; k++) hv[k] = g_pool[g * D + k];
    float h2[8];
#pragma unroll
    for (int j = 0; j < 8; j++) {
        float s = bfc1[j];
#pragma unroll
        for (int k = 0; k < D; k++) s = fmaf(hv[k], Wfc1[k * 8 + j], s);
        h2[j] = fmaxf(s, 0.f);
    }
    float o[4];
    float m = -1e30f;
#pragma unroll
    for (int j = 0; j < 4; j++) {
        float s = bout[j];
#pragma unroll
        for (int k = 0; k < 8; k++) s = fmaf(h2[k], Wout[k * 4 + j], s);
        o[j] = fmaxf(s, 0.f);
        if (o[j] > m) m = o[j];
    }
    float e[4]; float sum = 0.f;
#pragma unroll
    for (int j = 0; j < 4; j++) { e[j] = expf(o[j] - m); sum += e[j]; }
#pragma unroll
    for (int j = 0; j < 4; j++) out[g * 4 + j] = e[j] / sum;
}

// ------------------------------------------------------------------
extern "C" void kernel_launch(void* const* d_in, const int* in_sizes, int n_in,
                              void* d_out, int out_size) {
    const float* x    = (const float*)d_in[0];
    const float* Wn0  = (const float*)d_in[1];
    const float* bn0  = (const float*)d_in[2];
    const float* Ws0  = (const float*)d_in[3];
    const float* Wn   = (const float*)d_in[4];
    const float* bn   = (const float*)d_in[5];
    const float* Ws   = (const float*)d_in[6];
    const float* Wfc1 = (const float*)d_in[7];
    const float* bfc1 = (const float*)d_in[8];
    const float* Wout = (const float*)d_in[9];
    const float* bout = (const float*)d_in[10];
    const int*   src  = (const int*)d_in[11];
    const int*   dst  = (const int*)d_in[12];
    const int*   gid  = (const int*)d_in[13];
    float* out = (float*)d_out;

    zero_kernel<<<(NPAD + 255) / 256, 256>>>();
    hist_kernel<<<(NE / 4 + 255) / 256, 256>>>(dst);
    scan_all<<<1, 1024>>>();
    scatter_kernel<<<(NE / 4 + 255) / 256, 256>>>(src, dst);

    gemm0_kernel<<<(NN + 63) / 64, 64>>>(x, Wn0, Ws0);

    agg_fused<<<(NN * 32 + 255) / 256, 256>>>(bn0,        Wn,             Ws,             0); // A->B
    agg_fused<<<(NN * 32 + 255) / 256, 256>>>(bn,         Wn + 1 * D * D, Ws + 1 * D * D, 1); // B->A
    agg_fused<<<(NN * 32 + 255) / 256, 256>>>(bn + 1 * D, Wn + 2 * D * D, Ws + 2 * D * D, 0); // A->B
    agg_last <<<(NN * 32 + 255) / 256, 256>>>(bn + 2 * D, 1);

    pool_kernel<<<(NN + 1023) / 1024, 256>>>(gid);
    mlp_kernel<<<1, 64>>>(Wfc1, bfc1, Wout, bout, out);
}

// round 6
// speedup vs baseline: 1.0335x; 1.0335x over previous
#include <cuda_runtime.h>
#include <math.h>

#define NN 100000
#define NE 3200000
#define NG 64
#define D 32
#define INF 128
#define NPAD 102400   // 1024 threads * 100 counters

// ---- scratch ----
__device__ float g_rhs[NN * D];
__device__ float g_self[NN * D];
__device__ float g_h[NN * D];
__device__ float g_pool[NG * D];
__device__ int   g_counts[NPAD];
__device__ int   g_offs[NPAD + 1];
__device__ int   g_cursor[NPAD];
__device__ int   g_csrc[NE];

// ------------------------------------------------------------------
__global__ void zero_kernel() {
    int i = blockIdx.x * blockDim.x + threadIdx.x;
    if (i < NPAD) g_counts[i] = 0;
    if (i < NG * D) g_pool[i] = 0.f;
}

__global__ void hist_kernel(const int* __restrict__ dst) {
    int i = blockIdx.x * blockDim.x + threadIdx.x;
    int b = i * 4;
    if (b < NE) {
        int4 d = *(const int4*)&dst[b];
        atomicAdd(&g_counts[d.x], 1);
        atomicAdd(&g_counts[d.y], 1);
        atomicAdd(&g_counts[d.z], 1);
        atomicAdd(&g_counts[d.w], 1);
    }
}

// single-block scan: 1024 threads x 100 contiguous counters each
__global__ void __launch_bounds__(1024) scan_all() {
    const int CH = 100;
    int tid = threadIdx.x;
    int lane = tid & 31, wid = tid >> 5;
    int base = tid * CH;
    int s = 0;
#pragma unroll
    for (int i = 0; i < CH; i += 4) {
        int4 v = *(const int4*)&g_counts[base + i];
        s += v.x + v.y + v.z + v.w;
    }
    int pre = s;
#pragma unroll
    for (int dd = 1; dd < 32; dd <<= 1) {
        int t = __shfl_up_sync(0xffffffffu, pre, dd);
        if (lane >= dd) pre += t;
    }
    __shared__ int wsum[32];
    if (lane == 31) wsum[wid] = pre;
    __syncthreads();
    if (wid == 0) {
        int v = wsum[lane];
        int p = v;
#pragma unroll
        for (int dd = 1; dd < 32; dd <<= 1) {
            int t = __shfl_up_sync(0xffffffffu, p, dd);
            if (lane >= dd) p += t;
        }
        wsum[lane] = p - v;
    }
    __syncthreads();
    int run = wsum[wid] + (pre - s);
#pragma unroll
    for (int i = 0; i < CH; i += 4) {
        int4 c = *(const int4*)&g_counts[base + i];
        int4 o;
        o.x = run; run += c.x;
        o.y = run; run += c.y;
        o.z = run; run += c.z;
        o.w = run; run += c.w;
        *(int4*)&g_offs[base + i]   = o;
        *(int4*)&g_cursor[base + i] = o;
    }
}

__global__ void scatter_kernel(const int* __restrict__ src, const int* __restrict__ dst) {
    int i = blockIdx.x * blockDim.x + threadIdx.x;
    int b = i * 4;
    if (b < NE) {
        int4 s4 = *(const int4*)&src[b];
        int4 d4 = *(const int4*)&dst[b];
        int p;
        p = atomicAdd(&g_cursor[d4.x], 1); g_csrc[p] = s4.x;
        p = atomicAdd(&g_cursor[d4.y], 1); g_csrc[p] = s4.y;
        p = atomicAdd(&g_cursor[d4.z], 1); g_csrc[p] = s4.z;
        p = atomicAdd(&g_cursor[d4.w], 1); g_csrc[p] = s4.w;
    }
}

// ------------------------------------------------------------------
// Layer 0: rhs = x@Wn0, self = x@Ws0  (register blocked: 4 nodes x 16 cols/thread).
__global__ void __launch_bounds__(64) gemm0_kernel(const float* __restrict__ x,
                                                   const float* __restrict__ Wn0,
                                                   const float* __restrict__ Ws0) {
    __shared__ float Wsh[INF][64];
    __shared__ float xs[64][33];
    int tid = threadIdx.x;
    for (int idx = tid; idx < INF * D; idx += 64) {
        int k = idx >> 5, c = idx & 31;
        Wsh[k][c]      = Wn0[idx];
        Wsh[k][c + 32] = Ws0[idx];
    }
    int n0 = blockIdx.x * 64;
    int ng = tid >> 2, cg = tid & 3;
    int c0 = cg * 16;
    float acc[4][16];
#pragma unroll
    for (int i = 0; i < 4; i++)
#pragma unroll
        for (int j = 0; j < 16; j++) acc[i][j] = 0.f;

    for (int kt = 0; kt < 4; kt++) {
        __syncthreads();
        for (int idx = tid; idx < 64 * 32; idx += 64) {
            int nl = idx >> 5, j = idx & 31;
            int n = n0 + nl;
            xs[nl][j] = (n < NN) ? x[n * INF + kt * 32 + j] : 0.f;
        }
        __syncthreads();
#pragma unroll 4
        for (int k = 0; k < 32; k++) {
            float xv[4];
#pragma unroll
            for (int i = 0; i < 4; i++) xv[i] = xs[ng * 4 + i][k];
            const float* wrow = &Wsh[kt * 32 + k][c0];
            float4 w0 = *(const float4*)&wrow[0];
            float4 w1 = *(const float4*)&wrow[4];
            float4 w2 = *(const float4*)&wrow[8];
            float4 w3 = *(const float4*)&wrow[12];
#pragma unroll
            for (int i = 0; i < 4; i++) {
                float xi = xv[i];
                acc[i][0]  = fmaf(xi, w0.x, acc[i][0]);
                acc[i][1]  = fmaf(xi, w0.y, acc[i][1]);
                acc[i][2]  = fmaf(xi, w0.z, acc[i][2]);
                acc[i][3]  = fmaf(xi, w0.w, acc[i][3]);
                acc[i][4]  = fmaf(xi, w1.x, acc[i][4]);
                acc[i][5]  = fmaf(xi, w1.y, acc[i][5]);
                acc[i][6]  = fmaf(xi, w1.z, acc[i][6]);
                acc[i][7]  = fmaf(xi, w1.w, acc[i][7]);
                acc[i][8]  = fmaf(xi, w2.x, acc[i][8]);
                acc[i][9]  = fmaf(xi, w2.y, acc[i][9]);
                acc[i][10] = fmaf(xi, w2.z, acc[i][10]);
                acc[i][11] = fmaf(xi, w2.w, acc[i][11]);
                acc[i][12] = fmaf(xi, w3.x, acc[i][12]);
                acc[i][13] = fmaf(xi, w3.y, acc[i][13]);
                acc[i][14] = fmaf(xi, w3.z, acc[i][14]);
                acc[i][15] = fmaf(xi, w3.w, acc[i][15]);
            }
        }
    }
#pragma unroll
    for (int i = 0; i < 4; i++) {
        int n = n0 + ng * 4 + i;
        if (n >= NN) break;
        float* dstp = (cg < 2) ? &g_rhs[n * D + c0] : &g_self[n * D + (c0 - 32)];
#pragma unroll
        for (int j = 0; j < 4; j++) {
            float4 f = make_float4(acc[i][4 * j], acc[i][4 * j + 1],
                                   acc[i][4 * j + 2], acc[i][4 * j + 3]);
            *(float4*)&dstp[4 * j] = f;
        }
    }
}

// Layers 1..3: rhs = h@Wn_l, self = h@Ws_l  (register blocked, K=32, input g_h).
__global__ void __launch_bounds__(64) gemm_small_kernel(const float* __restrict__ Wn_l,
                                                        const float* __restrict__ Ws_l) {
    __shared__ float Wsh[D][64];
    __shared__ float xs[64][33];
    int tid = threadIdx.x;
    for (int idx = tid; idx < D * D; idx += 64) {
        int k = idx >> 5, c = idx & 31;
        Wsh[k][c]      = Wn_l[idx];
        Wsh[k][c + 32] = Ws_l[idx];
    }
    int n0 = blockIdx.x * 64;
    for (int idx = tid; idx < 64 * 32; idx += 64) {
        int nl = idx >> 5, j = idx & 31;
        int n = n0 + nl;
        xs[nl][j] = (n < NN) ? g_h[n * D + j] : 0.f;
    }
    __syncthreads();
    int ng = tid >> 2, cg = tid & 3;
    int c0 = cg * 16;
    float acc[4][16];
#pragma unroll
    for (int i = 0; i < 4; i++)
#pragma unroll
        for (int j = 0; j < 16; j++) acc[i][j] = 0.f;

#pragma unroll 4
    for (int k = 0; k < 32; k++) {
        float xv[4];
#pragma unroll
        for (int i = 0; i < 4; i++) xv[i] = xs[ng * 4 + i][k];
        const float* wrow = &Wsh[k][c0];
        float4 w0 = *(const float4*)&wrow[0];
        float4 w1 = *(const float4*)&wrow[4];
        float4 w2 = *(const float4*)&wrow[8];
        float4 w3 = *(const float4*)&wrow[12];
#pragma unroll
        for (int i = 0; i < 4; i++) {
            float xi = xv[i];
            acc[i][0]  = fmaf(xi, w0.x, acc[i][0]);
            acc[i][1]  = fmaf(xi, w0.y, acc[i][1]);
            acc[i][2]  = fmaf(xi, w0.z, acc[i][2]);
            acc[i][3]  = fmaf(xi, w0.w, acc[i][3]);
            acc[i][4]  = fmaf(xi, w1.x, acc[i][4]);
            acc[i][5]  = fmaf(xi, w1.y, acc[i][5]);
            acc[i][6]  = fmaf(xi, w1.z, acc[i][6]);
            acc[i][7]  = fmaf(xi, w1.w, acc[i][7]);
            acc[i][8]  = fmaf(xi, w2.x, acc[i][8]);
            acc[i][9]  = fmaf(xi, w2.y, acc[i][9]);
            acc[i][10] = fmaf(xi, w2.z, acc[i][10]);
            acc[i][11] = fmaf(xi, w2.w, acc[i][11]);
            acc[i][12] = fmaf(xi, w3.x, acc[i][12]);
            acc[i][13] = fmaf(xi, w3.y, acc[i][13]);
            acc[i][14] = fmaf(xi, w3.z, acc[i][14]);
            acc[i][15] = fmaf(xi, w3.w, acc[i][15]);
        }
    }
#pragma unroll
    for (int i = 0; i < 4; i++) {
        int n = n0 + ng * 4 + i;
        if (n >= NN) break;
        float* dstp = (cg < 2) ? &g_rhs[n * D + c0] : &g_self[n * D + (c0 - 32)];
#pragma unroll
        for (int j = 0; j < 4; j++) {
            float4 f = make_float4(acc[i][4 * j], acc[i][4 * j + 1],
                                   acc[i][4 * j + 2], acc[i][4 * j + 3]);
            *(float4*)&dstp[4 * j] = f;
        }
    }
}

// ------------------------------------------------------------------
// Aggregation (R1-verified): warp per node, lane = dim.
// h = relu(sum_{e->n} rhs[src] + bn + self)
__global__ void __launch_bounds__(256) agg_kernel(const float* __restrict__ bn) {
    int w = (blockIdx.x * blockDim.x + threadIdx.x) >> 5;
    int lane = threadIdx.x & 31;
    if (w >= NN) return;
    int beg = g_offs[w], end = g_offs[w + 1];
    float acc = g_self[w * D + lane] + bn[lane];
    int e = beg;
    for (; e + 4 <= end; e += 4) {
        int s0 = g_csrc[e], s1 = g_csrc[e + 1], s2 = g_csrc[e + 2], s3 = g_csrc[e + 3];
        float v0 = g_rhs[s0 * D + lane];
        float v1 = g_rhs[s1 * D + lane];
        float v2 = g_rhs[s2 * D + lane];
        float v3 = g_rhs[s3 * D + lane];
        acc += v0; acc += v1; acc += v2; acc += v3;
    }
    for (; e < end; e++) acc += g_rhs[g_csrc[e] * D + lane];
    g_h[w * D + lane] = fmaxf(acc, 0.f);
}

// ------------------------------------------------------------------
__global__ void __launch_bounds__(256) pool_kernel(const int* __restrict__ gid) {
    __shared__ float ps[NG * D];
    int tid = threadIdx.x;
    for (int i = tid; i < NG * D; i += 256) ps[i] = 0.f;
    __syncthreads();
    int d = tid & 31;
    int base = blockIdx.x * 1024;
    for (int i = tid >> 5; i < 1024; i += 8) {
        int n = base + i;
        if (n < NN) atomicAdd(&ps[gid[n] * D + d], g_h[n * D + d]);
    }
    __syncthreads();
    for (int i = tid; i < NG * D; i += 256) {
        float v = ps[i];
        if (v != 0.f) atomicAdd(&g_pool[i], v);
    }
}

__global__ void mlp_kernel(const float* __restrict__ Wfc1, const float* __restrict__ bfc1,
                           const float* __restrict__ Wout, const float* __restrict__ bout,
                           float* __restrict__ out) {
    int g = threadIdx.x;
    if (g >= NG) return;
    float hv[D];
#pragma unroll
    for (int k = 0; k < D; k++) hv[k] = g_pool[g * D + k];
    float h2[8];
#pragma unroll
    for (int j = 0; j < 8; j++) {
        float s = bfc1[j];
#pragma unroll
        for (int k = 0; k < D; k++) s = fmaf(hv[k], Wfc1[k * 8 + j], s);
        h2[j] = fmaxf(s, 0.f);
    }
    float o[4];
    float m = -1e30f;
#pragma unroll
    for (int j = 0; j < 4; j++) {
        float s = bout[j];
#pragma unroll
        for (int k = 0; k < 8; k++) s = fmaf(h2[k], Wout[k * 4 + j], s);
        o[j] = fmaxf(s, 0.f);
        if (o[j] > m) m = o[j];
    }
    float e[4]; float sum = 0.f;
#pragma unroll
    for (int j = 0; j < 4; j++) { e[j] = expf(o[j] - m); sum += e[j]; }
#pragma unroll
    for (int j = 0; j < 4; j++) out[g * 4 + j] = e[j] / sum;
}

// ------------------------------------------------------------------
extern "C" void kernel_launch(void* const* d_in, const int* in_sizes, int n_in,
                              void* d_out, int out_size) {
    const float* x    = (const float*)d_in[0];
    const float* Wn0  = (const float*)d_in[1];
    const float* bn0  = (const float*)d_in[2];
    const float* Ws0  = (const float*)d_in[3];
    const float* Wn   = (const float*)d_in[4];
    const float* bn   = (const float*)d_in[5];
    const float* Ws   = (const float*)d_in[6];
    const float* Wfc1 = (const float*)d_in[7];
    const float* bfc1 = (const float*)d_in[8];
    const float* Wout = (const float*)d_in[9];
    const float* bout = (const float*)d_in[10];
    const int*   src  = (const int*)d_in[11];
    const int*   dst  = (const int*)d_in[12];
    const int*   gid  = (const int*)d_in[13];
    float* out = (float*)d_out;

    zero_kernel<<<(NPAD + 255) / 256, 256>>>();
    hist_kernel<<<(NE / 4 + 255) / 256, 256>>>(dst);
    scan_all<<<1, 1024>>>();
    scatter_kernel<<<(NE / 4 + 255) / 256, 256>>>(src, dst);

    gemm0_kernel<<<(NN + 63) / 64, 64>>>(x, Wn0, Ws0);
    agg_kernel<<<(NN * 32 + 255) / 256, 256>>>(bn0);

    for (int l = 0; l < 3; l++) {
        gemm_small_kernel<<<(NN + 63) / 64, 64>>>(Wn + l * D * D, Ws + l * D * D);
        agg_kernel<<<(NN * 32 + 255) / 256, 256>>>(bn + l * D);
    }

    pool_kernel<<<(NN + 1023) / 1024, 256>>>(gid);
    mlp_kernel<<<1, 64>>>(Wfc1, bfc1, Wout, bout, out);
}